// round 1
// baseline (speedup 1.0000x reference)
#include <cuda_runtime.h>
#include <math.h>

namespace {

constexpr int B    = 4;
constexpr int S    = 2048;
constexpr int DIN  = 1024;
constexpr int DOUT = 1024;
constexpr int NH   = 16;
constexpr int HD   = 64;
constexpr int M    = B * S;            // 8192 rows

// ---- scratch (static device memory: allowed) ----
__device__ float g_q[(size_t)B * NH * S * HD];    // [B,H,S,HD]
__device__ float g_k[(size_t)B * NH * S * HD];
__device__ float g_v[(size_t)B * NH * S * HD];
__device__ float g_ctx[(size_t)M * DOUT];         // [B*S, DOUT] (head-interleaved cols)

// ============================================================
// GEMM:  C[m,n] = sum_k A[m,k] * W[n,k]  (+bias)   (NT gemm)
// A row-major [M,K], W row-major [N,K].
// head_layout=1 -> write C into [B,H,S,HD] layout instead.
// ============================================================
constexpr int BM = 64, BN = 64, BK = 32;

__global__ __launch_bounds__(256) void gemm_nt_kernel(
    const float* __restrict__ A, const float* __restrict__ W,
    float* __restrict__ C, const float* __restrict__ bias,
    int K, int N, int head_layout)
{
    __shared__ float As[BM][BK + 1];
    __shared__ float Ws[BN][BK + 1];

    const int tid = threadIdx.x;
    const int tx = tid & 15;          // 0..15 -> 4 output cols each
    const int ty = tid >> 4;          // 0..15 -> 4 output rows each
    const int m0 = blockIdx.y * BM;
    const int n0 = blockIdx.x * BN;

    float acc[4][4] = {};

    for (int k0 = 0; k0 < K; k0 += BK) {
        // load 64x32 tiles of A and W (float4 gmem, scalar smem stores)
#pragma unroll
        for (int p = 0; p < 2; p++) {
            int idx = p * 256 + tid;          // 0..511 (float4 index)
            int row = idx >> 3;               // 0..63
            int c4  = (idx & 7) << 2;         // 0,4,...,28
            float4 va = *reinterpret_cast<const float4*>(
                A + (size_t)(m0 + row) * K + k0 + c4);
            As[row][c4 + 0] = va.x; As[row][c4 + 1] = va.y;
            As[row][c4 + 2] = va.z; As[row][c4 + 3] = va.w;
            float4 vw = *reinterpret_cast<const float4*>(
                W + (size_t)(n0 + row) * K + k0 + c4);
            Ws[row][c4 + 0] = vw.x; Ws[row][c4 + 1] = vw.y;
            Ws[row][c4 + 2] = vw.z; Ws[row][c4 + 3] = vw.w;
        }
        __syncthreads();

#pragma unroll
        for (int k = 0; k < BK; k++) {
            float a[4], b[4];
#pragma unroll
            for (int i = 0; i < 4; i++) a[i] = As[ty * 4 + i][k];
#pragma unroll
            for (int j = 0; j < 4; j++) b[j] = Ws[tx * 4 + j][k];
#pragma unroll
            for (int i = 0; i < 4; i++)
#pragma unroll
                for (int j = 0; j < 4; j++)
                    acc[i][j] = fmaf(a[i], b[j], acc[i][j]);
        }
        __syncthreads();
    }

#pragma unroll
    for (int i = 0; i < 4; i++) {
#pragma unroll
        for (int j = 0; j < 4; j++) {
            int m = m0 + ty * 4 + i;
            int n = n0 + tx * 4 + j;
            float v = acc[i][j];
            if (bias) v += bias[n];
            if (!head_layout) {
                C[(size_t)m * N + n] = v;
            } else {
                int bb = m / S, ss = m - bb * S;
                int h  = n / HD, d = n - h * HD;
                C[(((size_t)(bb * NH + h) * S) + ss) * HD + d] = v;
            }
        }
    }
}

// ============================================================
// Causal flash attention, fp32.
// Q/K/V in [B*H, S, HD]; ctx out in [B*S, DOUT] with col h*HD+d.
// BQ=BKV=64 tiles; online softmax; O in registers.
// ============================================================
constexpr int BQ  = 64;
constexpr int BKV = 64;
constexpr int PAD = 68;   // smem row stride (floats); 16B-aligned, mild conflicts

__global__ __launch_bounds__(256) void attn_kernel(
    const float* __restrict__ Q, const float* __restrict__ Kp,
    const float* __restrict__ Vp, float* __restrict__ ctx)
{
    extern __shared__ float sm[];
    float (*Qs)[PAD] = reinterpret_cast<float(*)[PAD]>(sm);
    float (*Ks)[PAD] = reinterpret_cast<float(*)[PAD]>(sm + 1 * BQ * PAD);
    float (*Vs)[PAD] = reinterpret_cast<float(*)[PAD]>(sm + 2 * BQ * PAD);
    float (*Ps)[PAD] = reinterpret_cast<float(*)[PAD]>(sm + 3 * BQ * PAD);

    __shared__ float m_s[BQ], l_s[BQ], alpha_s[BQ];

    const int tid = threadIdx.x;
    const int tx = tid & 15;
    const int ty = tid >> 4;
    const int qt = blockIdx.x;           // query tile (0..31)
    const int bh = blockIdx.y;           // b*NH + h

    const float* qb = Q  + (size_t)bh * S * HD + (size_t)qt * BQ * HD;
    const float* kb = Kp + (size_t)bh * S * HD;
    const float* vb = Vp + (size_t)bh * S * HD;

    // load Q tile, fold in softmax scale 1/sqrt(HD)=0.125
    for (int i = tid; i < BQ * HD / 4; i += 256) {
        int row = i >> 4;
        int c4  = (i & 15) << 2;
        float4 v = *reinterpret_cast<const float4*>(qb + row * HD + c4);
        Qs[row][c4 + 0] = v.x * 0.125f;
        Qs[row][c4 + 1] = v.y * 0.125f;
        Qs[row][c4 + 2] = v.z * 0.125f;
        Qs[row][c4 + 3] = v.w * 0.125f;
    }
    if (tid < BQ) { m_s[tid] = -1e30f; l_s[tid] = 0.f; }

    float o[4][4] = {};
    __syncthreads();

    for (int kt = 0; kt <= qt; kt++) {
        // load K, V tiles
        const float* kt_ptr = kb + (size_t)kt * BKV * HD;
        const float* vt_ptr = vb + (size_t)kt * BKV * HD;
        for (int i = tid; i < BKV * HD / 4; i += 256) {
            int row = i >> 4;
            int c4  = (i & 15) << 2;
            float4 vk = *reinterpret_cast<const float4*>(kt_ptr + row * HD + c4);
            Ks[row][c4 + 0] = vk.x; Ks[row][c4 + 1] = vk.y;
            Ks[row][c4 + 2] = vk.z; Ks[row][c4 + 3] = vk.w;
            float4 vv = *reinterpret_cast<const float4*>(vt_ptr + row * HD + c4);
            Vs[row][c4 + 0] = vv.x; Vs[row][c4 + 1] = vv.y;
            Vs[row][c4 + 2] = vv.z; Vs[row][c4 + 3] = vv.w;
        }
        __syncthreads();

        // scores: S = Qs @ Ks^T  (64x64x64)
        float s[4][4] = {};
#pragma unroll 8
        for (int k = 0; k < HD; k++) {
            float a[4], b[4];
#pragma unroll
            for (int i = 0; i < 4; i++) a[i] = Qs[ty * 4 + i][k];
#pragma unroll
            for (int j = 0; j < 4; j++) b[j] = Ks[tx * 4 + j][k];
#pragma unroll
            for (int i = 0; i < 4; i++)
#pragma unroll
                for (int j = 0; j < 4; j++)
                    s[i][j] = fmaf(a[i], b[j], s[i][j]);
        }

        if (kt == qt) {   // causal mask on diagonal tile
#pragma unroll
            for (int i = 0; i < 4; i++)
#pragma unroll
                for (int j = 0; j < 4; j++)
                    if (tx * 4 + j > ty * 4 + i) s[i][j] = -1e30f;
        }

#pragma unroll
        for (int i = 0; i < 4; i++)
#pragma unroll
            for (int j = 0; j < 4; j++)
                Ps[ty * 4 + i][tx * 4 + j] = s[i][j];
        __syncthreads();

        // online softmax row pass (one thread per row)
        if (tid < BQ) {
            int r = tid;
            float m_old = m_s[r];
            float mx = m_old;
#pragma unroll 8
            for (int j = 0; j < BKV; j++) mx = fmaxf(mx, Ps[r][j]);
            float alpha = __expf(m_old - mx);
            float sum = 0.f;
#pragma unroll 8
            for (int j = 0; j < BKV; j++) {
                float p = __expf(Ps[r][j] - mx);
                Ps[r][j] = p;
                sum += p;
            }
            l_s[r] = l_s[r] * alpha + sum;
            m_s[r] = mx;
            alpha_s[r] = alpha;
        }
        __syncthreads();

        // O update: O = O*alpha + P @ V   (64x64x64)
        float al[4];
#pragma unroll
        for (int i = 0; i < 4; i++) al[i] = alpha_s[ty * 4 + i];
#pragma unroll
        for (int i = 0; i < 4; i++)
#pragma unroll
            for (int j = 0; j < 4; j++)
                o[i][j] *= al[i];
#pragma unroll 8
        for (int k = 0; k < BKV; k++) {
            float p[4], v[4];
#pragma unroll
            for (int i = 0; i < 4; i++) p[i] = Ps[ty * 4 + i][k];
#pragma unroll
            for (int j = 0; j < 4; j++) v[j] = Vs[k][tx * 4 + j];
#pragma unroll
            for (int i = 0; i < 4; i++)
#pragma unroll
                for (int j = 0; j < 4; j++)
                    o[i][j] = fmaf(p[i], v[j], o[i][j]);
        }
        __syncthreads();
    }

    // epilogue: normalize, write ctx [B*S, DOUT] at col h*HD+d
    const int h = bh % NH;
    const int bb = bh / NH;
#pragma unroll
    for (int i = 0; i < 4; i++) {
        int r = ty * 4 + i;
        float inv = 1.0f / l_s[r];
        int srow = qt * BQ + r;
#pragma unroll
        for (int j = 0; j < 4; j++) {
            ctx[((size_t)(bb * S + srow)) * DOUT + h * HD + tx * 4 + j] =
                o[i][j] * inv;
        }
    }
}

constexpr size_t ATTN_SMEM = (size_t)4 * BQ * PAD * sizeof(float);  // ~69.6 KB

}  // namespace

extern "C" void kernel_launch(void* const* d_in, const int* in_sizes, int n_in,
                              void* d_out, int out_size)
{
    (void)in_sizes; (void)n_in; (void)out_size;
    const float* x  = (const float*)d_in[0];
    const float* Wq = (const float*)d_in[1];
    const float* Wk = (const float*)d_in[2];
    const float* Wv = (const float*)d_in[3];
    const float* Wo = (const float*)d_in[4];
    const float* bo = (const float*)d_in[5];
    float* out = (float*)d_out;

    float *qp, *kp, *vp, *cp;
    cudaGetSymbolAddress((void**)&qp, g_q);
    cudaGetSymbolAddress((void**)&kp, g_k);
    cudaGetSymbolAddress((void**)&vp, g_v);
    cudaGetSymbolAddress((void**)&cp, g_ctx);

    cudaFuncSetAttribute(attn_kernel,
                         cudaFuncAttributeMaxDynamicSharedMemorySize,
                         (int)ATTN_SMEM);

    dim3 gemm_grid(DOUT / BN, M / BM);   // (16, 128)

    // Q, K, V projections -> [B,H,S,HD]
    gemm_nt_kernel<<<gemm_grid, 256>>>(x, Wq, qp, nullptr, DIN, DOUT, 1);
    gemm_nt_kernel<<<gemm_grid, 256>>>(x, Wk, kp, nullptr, DIN, DOUT, 1);
    gemm_nt_kernel<<<gemm_grid, 256>>>(x, Wv, vp, nullptr, DIN, DOUT, 1);

    // causal flash attention -> ctx [B*S, DOUT]
    dim3 attn_grid(S / BQ, B * NH);      // (32, 64)
    attn_kernel<<<attn_grid, 256, ATTN_SMEM>>>(qp, kp, vp, cp);

    // output projection + bias
    gemm_nt_kernel<<<gemm_grid, 256>>>(cp, Wo, out, bo, DOUT, DOUT, 0);
}

// round 2
// speedup vs baseline: 1.4952x; 1.4952x over previous
#include <cuda_runtime.h>
#include <math.h>

namespace {

constexpr int B    = 4;
constexpr int S    = 2048;
constexpr int DIN  = 1024;
constexpr int DOUT = 1024;
constexpr int NH   = 16;
constexpr int HD   = 64;
constexpr int M    = B * S;            // 8192 rows

// ---- scratch (static device memory: allowed) ----
__device__ float g_q[(size_t)B * NH * S * HD];    // [B,H,S,HD]
__device__ float g_k[(size_t)B * NH * S * HD];
__device__ float g_v[(size_t)B * NH * S * HD];
__device__ float g_ctx[(size_t)M * DOUT];         // [B*S, DOUT]

__device__ __forceinline__ unsigned f2tf32(float x) {
    unsigned u;
    asm("cvt.rna.tf32.f32 %0, %1;" : "=r"(u) : "f"(x));
    return u;
}

// ============================================================
// TF32 tensor-core GEMM:  C[m,n] = sum_k A[m,k] * W[n,k] (+bias)
// A row-major [M,K], W row-major [N,K] (= B col-major k x n).
// mma.sync.aligned.m16n8k8.row.col.f32.tf32.tf32.f32
// Block tile 128x64, BK=32, 8 warps in 4(m) x 2(n), warp tile 32x32.
// Double-buffered smem, gmem prefetch into registers.
// ============================================================
constexpr int GBM = 128, GBN = 64, GBK = 32, GPAD = 36;
constexpr size_t GEMM_SMEM = (size_t)(2 * GBM * GPAD + 2 * GBN * GPAD) * sizeof(float); // 55296

__global__ __launch_bounds__(256) void gemm_tf32_kernel(
    const float* __restrict__ A, const float* __restrict__ W,
    float* __restrict__ C, const float* __restrict__ bias,
    int K, int N, int head_layout)
{
    extern __shared__ float sm[];
    float* sA = sm;                        // [2][GBM][GPAD]
    float* sW = sm + 2 * GBM * GPAD;       // [2][GBN][GPAD]

    const int tid  = threadIdx.x;
    const int m0   = blockIdx.y * GBM;
    const int n0   = blockIdx.x * GBN;
    const int warp = tid >> 5, lane = tid & 31;
    const int wm = (warp >> 1) * 32;       // warp m offset in tile
    const int wn = (warp & 1) * 32;        // warp n offset in tile
    const int lr = lane >> 2, lc = lane & 3;

    float4 ra[4], rw[2];

    auto load_tile = [&](int k0) {
#pragma unroll
        for (int p = 0; p < 4; p++) {
            int idx = p * 256 + tid;
            int row = idx >> 3, c4 = (idx & 7) << 2;
            ra[p] = *reinterpret_cast<const float4*>(A + (size_t)(m0 + row) * K + k0 + c4);
        }
#pragma unroll
        for (int p = 0; p < 2; p++) {
            int idx = p * 256 + tid;
            int row = idx >> 3, c4 = (idx & 7) << 2;
            rw[p] = *reinterpret_cast<const float4*>(W + (size_t)(n0 + row) * K + k0 + c4);
        }
    };
    auto store_tile = [&](int buf) {
        float* dA = sA + buf * GBM * GPAD;
        float* dW = sW + buf * GBN * GPAD;
#pragma unroll
        for (int p = 0; p < 4; p++) {
            int idx = p * 256 + tid;
            int row = idx >> 3, c4 = (idx & 7) << 2;
            dA[row * GPAD + c4 + 0] = __uint_as_float(f2tf32(ra[p].x));
            dA[row * GPAD + c4 + 1] = __uint_as_float(f2tf32(ra[p].y));
            dA[row * GPAD + c4 + 2] = __uint_as_float(f2tf32(ra[p].z));
            dA[row * GPAD + c4 + 3] = __uint_as_float(f2tf32(ra[p].w));
        }
#pragma unroll
        for (int p = 0; p < 2; p++) {
            int idx = p * 256 + tid;
            int row = idx >> 3, c4 = (idx & 7) << 2;
            dW[row * GPAD + c4 + 0] = __uint_as_float(f2tf32(rw[p].x));
            dW[row * GPAD + c4 + 1] = __uint_as_float(f2tf32(rw[p].y));
            dW[row * GPAD + c4 + 2] = __uint_as_float(f2tf32(rw[p].z));
            dW[row * GPAD + c4 + 3] = __uint_as_float(f2tf32(rw[p].w));
        }
    };

    float acc[2][4][4] = {};

    load_tile(0);
    store_tile(0);
    const int NIT = K / GBK;
    for (int it = 0; it < NIT; ++it) {
        __syncthreads();
        if (it + 1 < NIT) load_tile((it + 1) * GBK);

        const float* bA = sA + (it & 1) * GBM * GPAD;
        const float* bW = sW + (it & 1) * GBN * GPAD;
#pragma unroll
        for (int kk = 0; kk < GBK; kk += 8) {
            unsigned af[2][4], bf[4][2];
#pragma unroll
            for (int mt = 0; mt < 2; mt++) {
                int r = wm + mt * 16 + lr;
                af[mt][0] = __float_as_uint(bA[r * GPAD + kk + lc]);
                af[mt][1] = __float_as_uint(bA[(r + 8) * GPAD + kk + lc]);
                af[mt][2] = __float_as_uint(bA[r * GPAD + kk + lc + 4]);
                af[mt][3] = __float_as_uint(bA[(r + 8) * GPAD + kk + lc + 4]);
            }
#pragma unroll
            for (int nt = 0; nt < 4; nt++) {
                int c = wn + nt * 8 + lr;
                bf[nt][0] = __float_as_uint(bW[c * GPAD + kk + lc]);
                bf[nt][1] = __float_as_uint(bW[c * GPAD + kk + lc + 4]);
            }
#pragma unroll
            for (int mt = 0; mt < 2; mt++)
#pragma unroll
                for (int nt = 0; nt < 4; nt++)
                    asm volatile(
                        "mma.sync.aligned.m16n8k8.row.col.f32.tf32.tf32.f32 "
                        "{%0,%1,%2,%3}, {%4,%5,%6,%7}, {%8,%9}, {%0,%1,%2,%3};"
                        : "+f"(acc[mt][nt][0]), "+f"(acc[mt][nt][1]),
                          "+f"(acc[mt][nt][2]), "+f"(acc[mt][nt][3])
                        : "r"(af[mt][0]), "r"(af[mt][1]), "r"(af[mt][2]), "r"(af[mt][3]),
                          "r"(bf[nt][0]), "r"(bf[nt][1]));
        }
        if (it + 1 < NIT) store_tile((it + 1) & 1);
    }

    // epilogue: C fragment: rows lr, lr+8; cols 2*lc, 2*lc+1
#pragma unroll
    for (int mt = 0; mt < 2; mt++) {
#pragma unroll
        for (int i = 0; i < 2; i++) {
            int m = m0 + wm + mt * 16 + lr + i * 8;
#pragma unroll
            for (int nt = 0; nt < 4; nt++) {
                int n = n0 + wn + nt * 8 + lc * 2;
                float v0 = acc[mt][nt][i * 2 + 0];
                float v1 = acc[mt][nt][i * 2 + 1];
                if (bias) { v0 += bias[n]; v1 += bias[n + 1]; }
                if (!head_layout) {
                    *reinterpret_cast<float2*>(&C[(size_t)m * N + n]) = make_float2(v0, v1);
                } else {
                    int h = n >> 6, d = n & 63;            // HD = 64
                    int bb = m >> 11, ss = m & 2047;       // S = 2048
                    *reinterpret_cast<float2*>(
                        &C[(((size_t)(bb * NH + h) * S) + ss) * HD + d]) = make_float2(v0, v1);
                }
            }
        }
    }
}

// ============================================================
// Causal flash attention, fp32 (unchanged math; softmax now
// 4 threads/row with shfl reductions instead of 1 thread/row).
// ============================================================
constexpr int BQ  = 64;
constexpr int BKV = 64;
constexpr int PAD = 68;

__global__ __launch_bounds__(256) void attn_kernel(
    const float* __restrict__ Q, const float* __restrict__ Kp,
    const float* __restrict__ Vp, float* __restrict__ ctx)
{
    extern __shared__ float sm[];
    float (*Qs)[PAD] = reinterpret_cast<float(*)[PAD]>(sm);
    float (*Ks)[PAD] = reinterpret_cast<float(*)[PAD]>(sm + 1 * BQ * PAD);
    float (*Vs)[PAD] = reinterpret_cast<float(*)[PAD]>(sm + 2 * BQ * PAD);
    float (*Ps)[PAD] = reinterpret_cast<float(*)[PAD]>(sm + 3 * BQ * PAD);

    __shared__ float m_s[BQ], l_s[BQ], alpha_s[BQ];

    const int tid = threadIdx.x;
    const int tx = tid & 15;
    const int ty = tid >> 4;
    const int qt = blockIdx.x;
    const int bh = blockIdx.y;

    const float* qb = Q  + (size_t)bh * S * HD + (size_t)qt * BQ * HD;
    const float* kb = Kp + (size_t)bh * S * HD;
    const float* vb = Vp + (size_t)bh * S * HD;

    for (int i = tid; i < BQ * HD / 4; i += 256) {
        int row = i >> 4;
        int c4  = (i & 15) << 2;
        float4 v = *reinterpret_cast<const float4*>(qb + row * HD + c4);
        Qs[row][c4 + 0] = v.x * 0.125f;
        Qs[row][c4 + 1] = v.y * 0.125f;
        Qs[row][c4 + 2] = v.z * 0.125f;
        Qs[row][c4 + 3] = v.w * 0.125f;
    }
    if (tid < BQ) { m_s[tid] = -1e30f; l_s[tid] = 0.f; }

    float o[4][4] = {};
    __syncthreads();

    for (int kt = 0; kt <= qt; kt++) {
        const float* kt_ptr = kb + (size_t)kt * BKV * HD;
        const float* vt_ptr = vb + (size_t)kt * BKV * HD;
        for (int i = tid; i < BKV * HD / 4; i += 256) {
            int row = i >> 4;
            int c4  = (i & 15) << 2;
            float4 vk = *reinterpret_cast<const float4*>(kt_ptr + row * HD + c4);
            Ks[row][c4 + 0] = vk.x; Ks[row][c4 + 1] = vk.y;
            Ks[row][c4 + 2] = vk.z; Ks[row][c4 + 3] = vk.w;
            float4 vv = *reinterpret_cast<const float4*>(vt_ptr + row * HD + c4);
            Vs[row][c4 + 0] = vv.x; Vs[row][c4 + 1] = vv.y;
            Vs[row][c4 + 2] = vv.z; Vs[row][c4 + 3] = vv.w;
        }
        __syncthreads();

        float s[4][4] = {};
#pragma unroll 8
        for (int k = 0; k < HD; k++) {
            float a[4], b[4];
#pragma unroll
            for (int i = 0; i < 4; i++) a[i] = Qs[ty * 4 + i][k];
#pragma unroll
            for (int j = 0; j < 4; j++) b[j] = Ks[tx * 4 + j][k];
#pragma unroll
            for (int i = 0; i < 4; i++)
#pragma unroll
                for (int j = 0; j < 4; j++)
                    s[i][j] = fmaf(a[i], b[j], s[i][j]);
        }

        if (kt == qt) {
#pragma unroll
            for (int i = 0; i < 4; i++)
#pragma unroll
                for (int j = 0; j < 4; j++)
                    if (tx * 4 + j > ty * 4 + i) s[i][j] = -1e30f;
        }

#pragma unroll
        for (int i = 0; i < 4; i++)
#pragma unroll
            for (int j = 0; j < 4; j++)
                Ps[ty * 4 + i][tx * 4 + j] = s[i][j];
        __syncthreads();

        // online softmax: 4 threads per row, shfl quad reduction
        {
            int r = tid >> 2;
            int part = tid & 3;
            float m_old = m_s[r];
            float mx = m_old;
#pragma unroll
            for (int j = 0; j < 16; j++) mx = fmaxf(mx, Ps[r][part * 16 + j]);
            mx = fmaxf(mx, __shfl_xor_sync(0xffffffffu, mx, 1));
            mx = fmaxf(mx, __shfl_xor_sync(0xffffffffu, mx, 2));
            float sum = 0.f;
#pragma unroll
            for (int j = 0; j < 16; j++) {
                float p = __expf(Ps[r][part * 16 + j] - mx);
                Ps[r][part * 16 + j] = p;
                sum += p;
            }
            sum += __shfl_xor_sync(0xffffffffu, sum, 1);
            sum += __shfl_xor_sync(0xffffffffu, sum, 2);
            if (part == 0) {
                float alpha = __expf(m_old - mx);
                l_s[r] = l_s[r] * alpha + sum;
                m_s[r] = mx;
                alpha_s[r] = alpha;
            }
        }
        __syncthreads();

        float al[4];
#pragma unroll
        for (int i = 0; i < 4; i++) al[i] = alpha_s[ty * 4 + i];
#pragma unroll
        for (int i = 0; i < 4; i++)
#pragma unroll
            for (int j = 0; j < 4; j++)
                o[i][j] *= al[i];
#pragma unroll 8
        for (int k = 0; k < BKV; k++) {
            float p[4], v[4];
#pragma unroll
            for (int i = 0; i < 4; i++) p[i] = Ps[ty * 4 + i][k];
#pragma unroll
            for (int j = 0; j < 4; j++) v[j] = Vs[k][tx * 4 + j];
#pragma unroll
            for (int i = 0; i < 4; i++)
#pragma unroll
                for (int j = 0; j < 4; j++)
                    o[i][j] = fmaf(p[i], v[j], o[i][j]);
        }
        __syncthreads();
    }

    const int h = bh % NH;
    const int bb = bh / NH;
#pragma unroll
    for (int i = 0; i < 4; i++) {
        int r = ty * 4 + i;
        float inv = 1.0f / l_s[r];
        int srow = qt * BQ + r;
#pragma unroll
        for (int j = 0; j < 4; j++) {
            ctx[((size_t)(bb * S + srow)) * DOUT + h * HD + tx * 4 + j] =
                o[i][j] * inv;
        }
    }
}

constexpr size_t ATTN_SMEM = (size_t)4 * BQ * PAD * sizeof(float);

}  // namespace

extern "C" void kernel_launch(void* const* d_in, const int* in_sizes, int n_in,
                              void* d_out, int out_size)
{
    (void)in_sizes; (void)n_in; (void)out_size;
    const float* x  = (const float*)d_in[0];
    const float* Wq = (const float*)d_in[1];
    const float* Wk = (const float*)d_in[2];
    const float* Wv = (const float*)d_in[3];
    const float* Wo = (const float*)d_in[4];
    const float* bo = (const float*)d_in[5];
    float* out = (float*)d_out;

    float *qp, *kp, *vp, *cp;
    cudaGetSymbolAddress((void**)&qp, g_q);
    cudaGetSymbolAddress((void**)&kp, g_k);
    cudaGetSymbolAddress((void**)&vp, g_v);
    cudaGetSymbolAddress((void**)&cp, g_ctx);

    cudaFuncSetAttribute(gemm_tf32_kernel,
                         cudaFuncAttributeMaxDynamicSharedMemorySize,
                         (int)GEMM_SMEM);
    cudaFuncSetAttribute(attn_kernel,
                         cudaFuncAttributeMaxDynamicSharedMemorySize,
                         (int)ATTN_SMEM);

    dim3 gemm_grid(DOUT / GBN, M / GBM);   // (16, 64)

    gemm_tf32_kernel<<<gemm_grid, 256, GEMM_SMEM>>>(x, Wq, qp, nullptr, DIN, DOUT, 1);
    gemm_tf32_kernel<<<gemm_grid, 256, GEMM_SMEM>>>(x, Wk, kp, nullptr, DIN, DOUT, 1);
    gemm_tf32_kernel<<<gemm_grid, 256, GEMM_SMEM>>>(x, Wv, vp, nullptr, DIN, DOUT, 1);

    dim3 attn_grid(S / BQ, B * NH);        // (32, 64)
    attn_kernel<<<attn_grid, 256, ATTN_SMEM>>>(qp, kp, vp, cp);

    gemm_tf32_kernel<<<gemm_grid, 256, GEMM_SMEM>>>(cp, Wo, out, bo, DOUT, DOUT, 0);
}

// round 3
// speedup vs baseline: 3.1202x; 2.0867x over previous
#include <cuda_runtime.h>
#include <math.h>

namespace {

constexpr int B    = 4;
constexpr int S    = 2048;
constexpr int DIN  = 1024;
constexpr int DOUT = 1024;
constexpr int NH   = 16;
constexpr int HD   = 64;
constexpr int M    = B * S;            // 8192 rows

// ---- scratch (static device memory: allowed) ----
__device__ float g_q[(size_t)B * NH * S * HD];    // [B,H,S,HD]
__device__ float g_k[(size_t)B * NH * S * HD];
__device__ float g_v[(size_t)B * NH * S * HD];
__device__ float g_ctx[(size_t)M * DOUT];         // [B*S, DOUT]

__device__ __forceinline__ unsigned f2tf32(float x) {
    unsigned u;
    asm("cvt.rna.tf32.f32 %0, %1;" : "=r"(u) : "f"(x));
    return u;
}

__device__ __forceinline__ void mma_tf32(
    float& c0, float& c1, float& c2, float& c3,
    unsigned a0, unsigned a1, unsigned a2, unsigned a3,
    unsigned b0, unsigned b1)
{
    asm volatile(
        "mma.sync.aligned.m16n8k8.row.col.f32.tf32.tf32.f32 "
        "{%0,%1,%2,%3}, {%4,%5,%6,%7}, {%8,%9}, {%0,%1,%2,%3};"
        : "+f"(c0), "+f"(c1), "+f"(c2), "+f"(c3)
        : "r"(a0), "r"(a1), "r"(a2), "r"(a3), "r"(b0), "r"(b1));
}

// ============================================================
// TF32 tensor-core GEMM (unchanged from round 2)
// ============================================================
constexpr int GBM = 128, GBN = 64, GBK = 32, GPAD = 36;
constexpr size_t GEMM_SMEM = (size_t)(2 * GBM * GPAD + 2 * GBN * GPAD) * sizeof(float);

__global__ __launch_bounds__(256) void gemm_tf32_kernel(
    const float* __restrict__ A, const float* __restrict__ W,
    float* __restrict__ C, const float* __restrict__ bias,
    int K, int N, int head_layout)
{
    extern __shared__ float sm[];
    float* sA = sm;
    float* sW = sm + 2 * GBM * GPAD;

    const int tid  = threadIdx.x;
    const int m0   = blockIdx.y * GBM;
    const int n0   = blockIdx.x * GBN;
    const int warp = tid >> 5, lane = tid & 31;
    const int wm = (warp >> 1) * 32;
    const int wn = (warp & 1) * 32;
    const int lr = lane >> 2, lc = lane & 3;

    float4 ra[4], rw[2];

    auto load_tile = [&](int k0) {
#pragma unroll
        for (int p = 0; p < 4; p++) {
            int idx = p * 256 + tid;
            int row = idx >> 3, c4 = (idx & 7) << 2;
            ra[p] = *reinterpret_cast<const float4*>(A + (size_t)(m0 + row) * K + k0 + c4);
        }
#pragma unroll
        for (int p = 0; p < 2; p++) {
            int idx = p * 256 + tid;
            int row = idx >> 3, c4 = (idx & 7) << 2;
            rw[p] = *reinterpret_cast<const float4*>(W + (size_t)(n0 + row) * K + k0 + c4);
        }
    };
    auto store_tile = [&](int buf) {
        float* dA = sA + buf * GBM * GPAD;
        float* dW = sW + buf * GBN * GPAD;
#pragma unroll
        for (int p = 0; p < 4; p++) {
            int idx = p * 256 + tid;
            int row = idx >> 3, c4 = (idx & 7) << 2;
            dA[row * GPAD + c4 + 0] = __uint_as_float(f2tf32(ra[p].x));
            dA[row * GPAD + c4 + 1] = __uint_as_float(f2tf32(ra[p].y));
            dA[row * GPAD + c4 + 2] = __uint_as_float(f2tf32(ra[p].z));
            dA[row * GPAD + c4 + 3] = __uint_as_float(f2tf32(ra[p].w));
        }
#pragma unroll
        for (int p = 0; p < 2; p++) {
            int idx = p * 256 + tid;
            int row = idx >> 3, c4 = (idx & 7) << 2;
            dW[row * GPAD + c4 + 0] = __uint_as_float(f2tf32(rw[p].x));
            dW[row * GPAD + c4 + 1] = __uint_as_float(f2tf32(rw[p].y));
            dW[row * GPAD + c4 + 2] = __uint_as_float(f2tf32(rw[p].z));
            dW[row * GPAD + c4 + 3] = __uint_as_float(f2tf32(rw[p].w));
        }
    };

    float acc[2][4][4] = {};

    load_tile(0);
    store_tile(0);
    const int NIT = K / GBK;
    for (int it = 0; it < NIT; ++it) {
        __syncthreads();
        if (it + 1 < NIT) load_tile((it + 1) * GBK);

        const float* bA = sA + (it & 1) * GBM * GPAD;
        const float* bW = sW + (it & 1) * GBN * GPAD;
#pragma unroll
        for (int kk = 0; kk < GBK; kk += 8) {
            unsigned af[2][4], bf[4][2];
#pragma unroll
            for (int mt = 0; mt < 2; mt++) {
                int r = wm + mt * 16 + lr;
                af[mt][0] = __float_as_uint(bA[r * GPAD + kk + lc]);
                af[mt][1] = __float_as_uint(bA[(r + 8) * GPAD + kk + lc]);
                af[mt][2] = __float_as_uint(bA[r * GPAD + kk + lc + 4]);
                af[mt][3] = __float_as_uint(bA[(r + 8) * GPAD + kk + lc + 4]);
            }
#pragma unroll
            for (int nt = 0; nt < 4; nt++) {
                int c = wn + nt * 8 + lr;
                bf[nt][0] = __float_as_uint(bW[c * GPAD + kk + lc]);
                bf[nt][1] = __float_as_uint(bW[c * GPAD + kk + lc + 4]);
            }
#pragma unroll
            for (int mt = 0; mt < 2; mt++)
#pragma unroll
                for (int nt = 0; nt < 4; nt++)
                    mma_tf32(acc[mt][nt][0], acc[mt][nt][1], acc[mt][nt][2], acc[mt][nt][3],
                             af[mt][0], af[mt][1], af[mt][2], af[mt][3],
                             bf[nt][0], bf[nt][1]);
        }
        if (it + 1 < NIT) store_tile((it + 1) & 1);
    }

#pragma unroll
    for (int mt = 0; mt < 2; mt++) {
#pragma unroll
        for (int i = 0; i < 2; i++) {
            int m = m0 + wm + mt * 16 + lr + i * 8;
#pragma unroll
            for (int nt = 0; nt < 4; nt++) {
                int n = n0 + wn + nt * 8 + lc * 2;
                float v0 = acc[mt][nt][i * 2 + 0];
                float v1 = acc[mt][nt][i * 2 + 1];
                if (bias) { v0 += bias[n]; v1 += bias[n + 1]; }
                if (!head_layout) {
                    *reinterpret_cast<float2*>(&C[(size_t)m * N + n]) = make_float2(v0, v1);
                } else {
                    int h = n >> 6, d = n & 63;
                    int bb = m >> 11, ss = m & 2047;
                    *reinterpret_cast<float2*>(
                        &C[(((size_t)(bb * NH + h) * S) + ss) * HD + d]) = make_float2(v0, v1);
                }
            }
        }
    }
}

// ============================================================
// Causal flash attention with tf32 mma for QK^T and P@V.
// 8 warps: 4(m) x 2(n) over the 64x64 tile; fp32 online softmax.
// ============================================================
constexpr int BQ  = 64;
constexpr int BKV = 64;
constexpr int PAD = 68;

__global__ __launch_bounds__(256) void attn_kernel(
    const float* __restrict__ Q, const float* __restrict__ Kp,
    const float* __restrict__ Vp, float* __restrict__ ctx)
{
    extern __shared__ float sm[];
    float (*Qs)[PAD] = reinterpret_cast<float(*)[PAD]>(sm);
    float (*Ks)[PAD] = reinterpret_cast<float(*)[PAD]>(sm + 1 * BQ * PAD);
    float (*Vs)[PAD] = reinterpret_cast<float(*)[PAD]>(sm + 2 * BQ * PAD);
    float (*Ps)[PAD] = reinterpret_cast<float(*)[PAD]>(sm + 3 * BQ * PAD);

    __shared__ float m_s[BQ], l_s[BQ], alpha_s[BQ];

    const int tid  = threadIdx.x;
    const int warp = tid >> 5, lane = tid & 31;
    const int wm = (warp >> 1) * 16;      // warp m offset (0,16,32,48)
    const int wn = (warp & 1) * 32;       // warp n offset (0,32)
    const int lr = lane >> 2, lc = lane & 3;
    const int qt = blockIdx.x;
    const int bh = blockIdx.y;

    const float* qb = Q  + (size_t)bh * S * HD + (size_t)qt * BQ * HD;
    const float* kb = Kp + (size_t)bh * S * HD;
    const float* vb = Vp + (size_t)bh * S * HD;

    // load Q tile: fold softmax scale, convert to tf32
    for (int i = tid; i < BQ * HD / 4; i += 256) {
        int row = i >> 4;
        int c4  = (i & 15) << 2;
        float4 v = *reinterpret_cast<const float4*>(qb + row * HD + c4);
        Qs[row][c4 + 0] = __uint_as_float(f2tf32(v.x * 0.125f));
        Qs[row][c4 + 1] = __uint_as_float(f2tf32(v.y * 0.125f));
        Qs[row][c4 + 2] = __uint_as_float(f2tf32(v.z * 0.125f));
        Qs[row][c4 + 3] = __uint_as_float(f2tf32(v.w * 0.125f));
    }
    if (tid < BQ) { m_s[tid] = -1e30f; l_s[tid] = 0.f; }

    float acc_o[4][4] = {};
    __syncthreads();

    for (int kt = 0; kt <= qt; kt++) {
        const float* kt_ptr = kb + (size_t)kt * BKV * HD;
        const float* vt_ptr = vb + (size_t)kt * BKV * HD;
        for (int i = tid; i < BKV * HD / 4; i += 256) {
            int row = i >> 4;
            int c4  = (i & 15) << 2;
            float4 vk = *reinterpret_cast<const float4*>(kt_ptr + row * HD + c4);
            Ks[row][c4 + 0] = __uint_as_float(f2tf32(vk.x));
            Ks[row][c4 + 1] = __uint_as_float(f2tf32(vk.y));
            Ks[row][c4 + 2] = __uint_as_float(f2tf32(vk.z));
            Ks[row][c4 + 3] = __uint_as_float(f2tf32(vk.w));
            float4 vv = *reinterpret_cast<const float4*>(vt_ptr + row * HD + c4);
            Vs[row][c4 + 0] = __uint_as_float(f2tf32(vv.x));
            Vs[row][c4 + 1] = __uint_as_float(f2tf32(vv.y));
            Vs[row][c4 + 2] = __uint_as_float(f2tf32(vv.z));
            Vs[row][c4 + 3] = __uint_as_float(f2tf32(vv.w));
        }
        __syncthreads();

        // ---- scores: S = Qs @ Ks^T  (tensor cores) ----
        float acc_s[4][4] = {};
#pragma unroll
        for (int kk = 0; kk < HD; kk += 8) {
            unsigned a0 = __float_as_uint(Qs[wm + lr][kk + lc]);
            unsigned a1 = __float_as_uint(Qs[wm + lr + 8][kk + lc]);
            unsigned a2 = __float_as_uint(Qs[wm + lr][kk + lc + 4]);
            unsigned a3 = __float_as_uint(Qs[wm + lr + 8][kk + lc + 4]);
#pragma unroll
            for (int nt = 0; nt < 4; nt++) {
                int c = wn + nt * 8 + lr;
                unsigned b0 = __float_as_uint(Ks[c][kk + lc]);
                unsigned b1 = __float_as_uint(Ks[c][kk + lc + 4]);
                mma_tf32(acc_s[nt][0], acc_s[nt][1], acc_s[nt][2], acc_s[nt][3],
                         a0, a1, a2, a3, b0, b1);
            }
        }
        // write scores to smem
#pragma unroll
        for (int nt = 0; nt < 4; nt++) {
            int c = wn + nt * 8 + lc * 2;
            *reinterpret_cast<float2*>(&Ps[wm + lr][c])     = make_float2(acc_s[nt][0], acc_s[nt][1]);
            *reinterpret_cast<float2*>(&Ps[wm + lr + 8][c]) = make_float2(acc_s[nt][2], acc_s[nt][3]);
        }
        __syncthreads();

        // ---- online softmax: 4 threads/row; mask diag tile; tf32 P ----
        {
            int r = tid >> 2;
            int part = tid & 3;
            bool diag = (kt == qt);
            float vals[16];
#pragma unroll
            for (int j = 0; j < 16; j++) {
                int col = part * 16 + j;
                float v = Ps[r][col];
                if (diag && col > r) v = -1e30f;
                vals[j] = v;
            }
            float m_old = m_s[r];
            float mx = m_old;
#pragma unroll
            for (int j = 0; j < 16; j++) mx = fmaxf(mx, vals[j]);
            mx = fmaxf(mx, __shfl_xor_sync(0xffffffffu, mx, 1));
            mx = fmaxf(mx, __shfl_xor_sync(0xffffffffu, mx, 2));
            float sum = 0.f;
#pragma unroll
            for (int j = 0; j < 16; j++) {
                float p = __uint_as_float(f2tf32(__expf(vals[j] - mx)));
                Ps[r][part * 16 + j] = p;
                sum += p;
            }
            sum += __shfl_xor_sync(0xffffffffu, sum, 1);
            sum += __shfl_xor_sync(0xffffffffu, sum, 2);
            if (part == 0) {
                float alpha = __expf(m_old - mx);
                l_s[r] = l_s[r] * alpha + sum;
                m_s[r] = mx;
                alpha_s[r] = alpha;
            }
        }
        __syncthreads();

        // ---- rescale O, then O += P @ V (tensor cores) ----
        {
            float al0 = alpha_s[wm + lr];
            float al1 = alpha_s[wm + lr + 8];
#pragma unroll
            for (int nt = 0; nt < 4; nt++) {
                acc_o[nt][0] *= al0; acc_o[nt][1] *= al0;
                acc_o[nt][2] *= al1; acc_o[nt][3] *= al1;
            }
        }
#pragma unroll
        for (int kk = 0; kk < BKV; kk += 8) {
            unsigned a0 = __float_as_uint(Ps[wm + lr][kk + lc]);
            unsigned a1 = __float_as_uint(Ps[wm + lr + 8][kk + lc]);
            unsigned a2 = __float_as_uint(Ps[wm + lr][kk + lc + 4]);
            unsigned a3 = __float_as_uint(Ps[wm + lr + 8][kk + lc + 4]);
#pragma unroll
            for (int nt = 0; nt < 4; nt++) {
                int c = wn + nt * 8 + lr;            // d column
                unsigned b0 = __float_as_uint(Vs[kk + lc][c]);      // V^T read
                unsigned b1 = __float_as_uint(Vs[kk + lc + 4][c]);
                mma_tf32(acc_o[nt][0], acc_o[nt][1], acc_o[nt][2], acc_o[nt][3],
                         a0, a1, a2, a3, b0, b1);
            }
        }
        __syncthreads();   // protect Ks/Vs before next iteration's load
    }

    // epilogue: normalize, write ctx [B*S, DOUT] at col h*HD+d
    const int h  = bh % NH;
    const int bb = bh / NH;
    {
        int r0 = wm + lr, r1 = wm + lr + 8;
        float inv0 = 1.0f / l_s[r0];
        float inv1 = 1.0f / l_s[r1];
        size_t row0 = (size_t)(bb * S + qt * BQ + r0) * DOUT + h * HD;
        size_t row1 = (size_t)(bb * S + qt * BQ + r1) * DOUT + h * HD;
#pragma unroll
        for (int nt = 0; nt < 4; nt++) {
            int c = wn + nt * 8 + lc * 2;
            *reinterpret_cast<float2*>(&ctx[row0 + c]) =
                make_float2(acc_o[nt][0] * inv0, acc_o[nt][1] * inv0);
            *reinterpret_cast<float2*>(&ctx[row1 + c]) =
                make_float2(acc_o[nt][2] * inv1, acc_o[nt][3] * inv1);
        }
    }
}

constexpr size_t ATTN_SMEM = (size_t)4 * BQ * PAD * sizeof(float);

}  // namespace

extern "C" void kernel_launch(void* const* d_in, const int* in_sizes, int n_in,
                              void* d_out, int out_size)
{
    (void)in_sizes; (void)n_in; (void)out_size;
    const float* x  = (const float*)d_in[0];
    const float* Wq = (const float*)d_in[1];
    const float* Wk = (const float*)d_in[2];
    const float* Wv = (const float*)d_in[3];
    const float* Wo = (const float*)d_in[4];
    const float* bo = (const float*)d_in[5];
    float* out = (float*)d_out;

    float *qp, *kp, *vp, *cp;
    cudaGetSymbolAddress((void**)&qp, g_q);
    cudaGetSymbolAddress((void**)&kp, g_k);
    cudaGetSymbolAddress((void**)&vp, g_v);
    cudaGetSymbolAddress((void**)&cp, g_ctx);

    cudaFuncSetAttribute(gemm_tf32_kernel,
                         cudaFuncAttributeMaxDynamicSharedMemorySize,
                         (int)GEMM_SMEM);
    cudaFuncSetAttribute(attn_kernel,
                         cudaFuncAttributeMaxDynamicSharedMemorySize,
                         (int)ATTN_SMEM);

    dim3 gemm_grid(DOUT / GBN, M / GBM);   // (16, 64)

    gemm_tf32_kernel<<<gemm_grid, 256, GEMM_SMEM>>>(x, Wq, qp, nullptr, DIN, DOUT, 1);
    gemm_tf32_kernel<<<gemm_grid, 256, GEMM_SMEM>>>(x, Wk, kp, nullptr, DIN, DOUT, 1);
    gemm_tf32_kernel<<<gemm_grid, 256, GEMM_SMEM>>>(x, Wv, vp, nullptr, DIN, DOUT, 1);

    dim3 attn_grid(S / BQ, B * NH);        // (32, 64)
    attn_kernel<<<attn_grid, 256, ATTN_SMEM>>>(qp, kp, vp, cp);

    gemm_tf32_kernel<<<gemm_grid, 256, GEMM_SMEM>>>(cp, Wo, out, bo, DOUT, DOUT, 0);
}